// round 11
// baseline (speedup 1.0000x reference)
#include <cuda_runtime.h>
#include <cstdint>
#include <cstddef>

#define BATCH 4096
#define T_SEQ 512
#define SDIM  16
#define ODIM  8
#define IDIM  4
#define RS    8
#define CH    64
#define LCH   8
#define NB    2
#define TPB   128
#define NTYPE 2

#define NT_Z  ((T_SEQ*ODIM/32)*(BATCH/32))   // 16384 transpose tiles for obs
#define NT_U  ((T_SEQ*IDIM/32)*(BATCH/32))   // 8192 tiles for u

typedef unsigned long long ull;

__device__ float g_M [RS*256];
__device__ float g_Kg[RS*128];
__device__ float g_Ng[RS*64];
__device__ float g_Phi[NTYPE*256];
__device__ float g_W  [NTYPE*16*96];            // [type][s][j*12 + q] (q: 0..7 z, 8..11 u)
__device__ float g_d [(size_t)CH*SDIM*BATCH];   // [c][s][b]
__device__ float g_xs[(size_t)CH*SDIM*BATCH];   // [c][s][b]
__device__ float g_tz[(size_t)T_SEQ*ODIM*BATCH]; // obs transposed [k][q][b]
__device__ float g_tu[(size_t)T_SEQ*IDIM*BATCH]; // u transposed [k][i][b]

// ---------- f32x2 helpers ----------
__device__ __forceinline__ ull fpair(float a, float b){
  ull r; asm("mov.b64 %0, {%1,%2};" : "=l"(r) : "f"(a), "f"(b)); return r;
}
__device__ __forceinline__ ull fdup(float a){ return fpair(a,a); }
__device__ __forceinline__ void unpack2(ull p, float& a, float& b){
  asm("mov.b64 {%0,%1}, %2;" : "=f"(a), "=f"(b) : "l"(p));
}
__device__ __forceinline__ void ffma2(ull& d, ull a, ull b){
  asm("fma.rn.f32x2 %0, %1, %2, %0;" : "+l"(d) : "l"(a), "l"(b));
}

// ---------- fully unrolled 4x4 inverse ----------
__device__ __forceinline__ void inv4x4(const float* m, int ld, float* inv){
  float a00=m[0],      a01=m[1],      a02=m[2],      a03=m[3];
  float a10=m[ld],     a11=m[ld+1],   a12=m[ld+2],   a13=m[ld+3];
  float a20=m[2*ld],   a21=m[2*ld+1], a22=m[2*ld+2], a23=m[2*ld+3];
  float a30=m[3*ld],   a31=m[3*ld+1], a32=m[3*ld+2], a33=m[3*ld+3];
  float s0=a00*a11-a01*a10, s1=a00*a12-a02*a10, s2=a00*a13-a03*a10;
  float s3=a01*a12-a02*a11, s4=a01*a13-a03*a11, s5=a02*a13-a03*a12;
  float c5=a22*a33-a23*a32, c4=a21*a33-a23*a31, c3=a21*a32-a22*a31;
  float c2=a20*a33-a23*a30, c1=a20*a32-a22*a30, c0=a20*a31-a21*a30;
  float det=s0*c5-s1*c4+s2*c3+s3*c2-s4*c1+s5*c0;
  float id=1.f/det;
  inv[0] =( a11*c5-a12*c4+a13*c3)*id;
  inv[1] =(-a01*c5+a02*c4-a03*c3)*id;
  inv[2] =( a31*s5-a32*s4+a33*s3)*id;
  inv[3] =(-a21*s5+a22*s4-a23*s3)*id;
  inv[4] =(-a10*c5+a12*c2-a13*c1)*id;
  inv[5] =( a00*c5-a02*c2+a03*c1)*id;
  inv[6] =(-a30*s5+a32*s2-a33*s1)*id;
  inv[7] =( a20*s5-a22*s2+a23*s1)*id;
  inv[8] =( a10*c4-a11*c2+a13*c0)*id;
  inv[9] =(-a00*c4+a01*c2-a03*c0)*id;
  inv[10]=( a30*s4-a31*s2+a33*s0)*id;
  inv[11]=(-a20*s4+a21*s2-a23*s0)*id;
  inv[12]=(-a10*c3+a11*c1-a12*c0)*id;
  inv[13]=( a00*c3-a01*c1+a02*c0)*id;
  inv[14]=(-a30*s3+a31*s1-a32*s0)*id;
  inv[15]=( a20*s3-a21*s1+a22*s0)*id;
}

// prep: block 0 = Riccati + W/Phi composition; blocks 1.. = input transposes (overlapped).
__global__ void __launch_bounds__(256) prep_kernel(const float* __restrict__ A_,
                                                   const float* __restrict__ B_,
                                                   const float* __restrict__ C_,
                                                   const float* __restrict__ Q_,
                                                   const float* __restrict__ R_,
                                                   const float* __restrict__ obs,
                                                   const float* __restrict__ u)
{
  __shared__ float sA[256], sQ[256], sC[128], sB[64], sR[64], sCA[128], sCB[32];
  __shared__ float P[256], Tm[256], Pp[256], CP[128], S8[64], Sinv[64], KK[128];
  __shared__ float BufA[256], BufB[256];
  __shared__ float tile[32][33];

  if (blockIdx.x != 0){
    // ---- transpose tile ----
    int bid = blockIdx.x - 1;
    const float* in; float* outp; int Rr, Cc, tile_id;
    if (bid < NT_Z){ in=obs; outp=g_tz; Rr=BATCH; Cc=T_SEQ*ODIM; tile_id=bid; }
    else           { in=u;   outp=g_tu; Rr=BATCH; Cc=T_SEQ*IDIM; tile_id=bid-NT_Z; }
    int ntx = Cc/32;
    int bx = tile_id % ntx, by = tile_id / ntx;
    int tx = threadIdx.x & 31, ty = threadIdx.x >> 5;   // ty 0..7
    int c  = bx*32 + tx;
    int r0 = by*32;
    #pragma unroll
    for (int j=0;j<32;j+=8)
      tile[ty+j][tx] = in[(size_t)(r0+ty+j)*Cc + c];
    __syncthreads();
    int r  = r0 + tx;
    int c0 = bx*32;
    #pragma unroll
    for (int j=0;j<32;j+=8)
      outp[(size_t)(c0+ty+j)*Rr + r] = tile[tx][ty+j];
    return;
  }

  // ---- Riccati block ----
  const int t = threadIdx.x;
  const int s = t>>4, j = t&15;

  sA[t]=A_[t]; sQ[t]=Q_[t];
  P[t] = (s==j)?1.f:0.f;
  if (t<128) sC[t]=C_[t];
  if (t<64){ sB[t]=B_[t]; sR[t]=R_[t]; }
  __syncthreads();
  if (t<128){ int o=t>>4, jj=t&15; float a=0.f;
    #pragma unroll
    for(int m=0;m<16;m++) a+=sC[o*16+m]*sA[m*16+jj];
    sCA[t]=a; }
  if (t<32){ int o=t>>2, ii=t&3; float a=0.f;
    #pragma unroll
    for(int m=0;m<16;m++) a+=sC[o*16+m]*sB[m*4+ii];
    sCB[t]=a; }
  __syncthreads();

  for (int k=0;k<RS;k++){
    { float a=0.f;                                    // Tm = A @ P
      #pragma unroll
      for(int m=0;m<16;m++) a+=sA[s*16+m]*P[m*16+j];
      Tm[t]=a; }
    __syncthreads();
    { float a=sQ[t];                                  // Pp = Tm A^T + Q
      #pragma unroll
      for(int m=0;m<16;m++) a+=Tm[s*16+m]*sA[j*16+m];
      Pp[t]=a; }
    __syncthreads();
    if (t<128){ int o=t>>4, jj=t&15; float a=0.f;     // CP = C @ Pp
      #pragma unroll
      for(int m=0;m<16;m++) a+=sC[o*16+m]*Pp[m*16+jj];
      CP[t]=a; }
    __syncthreads();
    if (t<64){ int o=t>>3, p=t&7; float a=sR[t];      // S = CP C^T + R
      #pragma unroll
      for(int m=0;m<16;m++) a+=CP[o*16+m]*sC[p*16+m];
      S8[t]=a; }
    __syncthreads();
    if (t==0){                                        // 8x8 SPD inverse via Schur
      float Ai[16]; inv4x4(&S8[0], 8, Ai);
      float W[16];
      #pragma unroll
      for(int i4=0;i4<4;i4++)
        #pragma unroll
        for(int j4=0;j4<4;j4++){ float a=0.f;
          #pragma unroll
          for(int m=0;m<4;m++) a+=S8[(4+i4)*8+m]*Ai[m*4+j4];
          W[i4*4+j4]=a; }
      float Sc[16];
      #pragma unroll
      for(int i4=0;i4<4;i4++)
        #pragma unroll
        for(int j4=0;j4<4;j4++){ float a=S8[(4+i4)*8+4+j4];
          #pragma unroll
          for(int m=0;m<4;m++) a-=W[i4*4+m]*S8[m*8+4+j4];
          Sc[i4*4+j4]=a; }
      float Sci[16]; inv4x4(Sc, 4, Sci);
      float X21[16];
      #pragma unroll
      for(int i4=0;i4<4;i4++)
        #pragma unroll
        for(int j4=0;j4<4;j4++){ float a=0.f;
          #pragma unroll
          for(int m=0;m<4;m++) a+=Sci[i4*4+m]*W[m*4+j4];
          X21[i4*4+j4]=-a; }
      float X11[16];
      #pragma unroll
      for(int i4=0;i4<4;i4++)
        #pragma unroll
        for(int j4=0;j4<4;j4++){ float a=Ai[i4*4+j4];
          #pragma unroll
          for(int m=0;m<4;m++) a-=W[m*4+i4]*X21[m*4+j4];
          X11[i4*4+j4]=a; }
      #pragma unroll
      for(int o=0;o<8;o++)
        #pragma unroll
        for(int p=0;p<8;p++){
          float v;
          if (o<4 && p<4) v=X11[o*4+p];
          else if (o<4)   v=X21[(p-4)*4+o];
          else if (p<4)   v=X21[(o-4)*4+p];
          else            v=Sci[(o-4)*4+(p-4)];
          Sinv[o*8+p]=v; }
    }
    __syncthreads();
    if (t<128){ int ss=t>>3, o=t&7; float a=0.f;      // K = CP^T Sinv
      #pragma unroll
      for(int p=0;p<8;p++) a+=CP[p*16+ss]*Sinv[p*8+o];
      KK[t]=a; }
    __syncthreads();
    { float a=Pp[t], mg=sA[t];                        // P_post, M_k
      #pragma unroll
      for(int o=0;o<8;o++){ float kv=KK[s*8+o]; a-=kv*CP[o*16+j]; mg-=kv*sCA[o*16+j]; }
      P[t]=a;
      g_M[k*256+t]=mg; }
    if (t<128) g_Kg[k*128+t]=KK[t];
    if (t<64){ int ss=t>>2, ii=t&3; float a=sB[t];    // N_k
      #pragma unroll
      for(int o=0;o<8;o++) a-=KK[ss*8+o]*sCB[o*4+ii];
      g_Ng[k*64+t]=a; }
    __syncthreads();
  }

  // Per chunk type tt: suffix products; Wz_j=S_j K_j, Wu_j=S_j N_j; Phi = full product
  for (int tt=0; tt<NTYPE; tt++){
    float* Sb = BufA; float* Sn = BufB;
    Sb[t] = (s==j)?1.f:0.f;
    __syncthreads();
    for (int jj=LCH-1; jj>=0; jj--){
      const int k = (tt==0)? jj : (RS-1);
      if (t<128){ int ss=t>>3, o=t&7; float a=0.f;    // Wz
        #pragma unroll
        for(int m=0;m<16;m++) a+=Sb[ss*16+m]*g_Kg[k*128+m*8+o];
        g_W[(tt*16+ss)*96 + jj*12 + o] = a; }
      else { int e=t-128; int ss=e>>2, ii=e&3;        // Wu
        if (e<64){ float a=0.f;
          #pragma unroll
          for(int m=0;m<16;m++) a+=Sb[ss*16+m]*g_Ng[k*64+m*4+ii];
          g_W[(tt*16+ss)*96 + jj*12 + 8 + ii] = a; } }
      { float a=0.f;                                  // S = S @ M_k
        #pragma unroll
        for(int m=0;m<16;m++) a+=Sb[s*16+m]*g_M[k*256+m*16+j];
        Sn[t]=a; }
      __syncthreads();
      float* tmp=Sb; Sb=Sn; Sn=tmp;
    }
    g_Phi[tt*256+t]=Sb[t];
    __syncthreads();
  }
}

// P1: chunk response from zero state — d[c][:][b] = W(type) @ inputs(chunk c, batch b)
__global__ void __launch_bounds__(TPB) resp_kernel(void)
{
  __shared__ ull sW[16*96];                           // duplicated pairs, 12KB
  const int c  = blockIdx.y;
  const int tt = (c==0)?0:1;
  for (int idx=threadIdx.x; idx<16*96; idx+=TPB)
    sW[idx] = fdup(g_W[tt*16*96 + idx]);
  const int b0 = (blockIdx.x*TPB + threadIdx.x)*NB;
  const int k0 = c*LCH;
  ull acc[SDIM];
  #pragma unroll
  for (int s=0;s<SDIM;s++) acc[s]=0ull;
  __syncthreads();

  for (int jj=0;jj<LCH;jj++){
    ull ip[12];
    #pragma unroll
    for (int q=0;q<8;q++)
      ip[q] = *(const ull*)&g_tz[((size_t)(k0+jj)*8+q)*BATCH + b0];
    #pragma unroll
    for (int q=0;q<4;q++)
      ip[8+q] = *(const ull*)&g_tu[((size_t)(k0+jj)*4+q)*BATCH + b0];
    #pragma unroll
    for (int s=0;s<SDIM;s++){
      const ulonglong2* Wr = (const ulonglong2*)&sW[s*96 + jj*12];
      ull a = acc[s];
      #pragma unroll
      for (int q=0;q<6;q++){
        ulonglong2 w = Wr[q];
        ffma2(a, w.x, ip[2*q]);
        ffma2(a, w.y, ip[2*q+1]);
      }
      acc[s]=a;
    }
  }
  #pragma unroll
  for (int s=0;s<SDIM;s++)
    *(ull*)&g_d[((size_t)(c*SDIM+s))*BATCH + b0] = acc[s];
}

// P2: exact serial combine across chunks, one thread per batch.
__global__ void __launch_bounds__(TPB) pass2_kernel(const float* __restrict__ x0)
{
  __shared__ float sPhi[NTYPE*256];
  for (int e=threadIdx.x; e<NTYPE*256; e+=TPB) sPhi[e]=g_Phi[e];
  const int b = blockIdx.x*TPB + threadIdx.x;
  float x[16];
  #pragma unroll
  for(int s=0;s<16;s++) x[s]=x0[s];
  __syncthreads();
  #pragma unroll
  for(int s=0;s<16;s++) g_xs[(size_t)s*BATCH + b]=x[s];
  for (int c=1;c<CH;c++){
    int pidx = (c-1==0)?0:1;
    const float* Phi=&sPhi[pidx*256];
    float dd[16];
    #pragma unroll
    for(int s=0;s<16;s++) dd[s]=g_d[((size_t)((c-1)*16+s))*BATCH + b];
    float xn[16];
    #pragma unroll
    for(int s=0;s<16;s++){
      float a=dd[s];
      #pragma unroll
      for(int jj=0;jj<16;jj++) a+=Phi[s*16+jj]*x[jj];
      xn[s]=a;
    }
    #pragma unroll
    for(int s=0;s<16;s++) x[s]=xn[s];
    #pragma unroll
    for(int s=0;s<16;s++) g_xs[((size_t)(c*16+s))*BATCH + b]=x[s];
  }
}

// P3 (R9 body, verbatim): serial recurrence within chunk from true start state.
__global__ void __launch_bounds__(TPB, 4) pass3_kernel(const float* __restrict__ obs,
                                                       const float* __restrict__ u,
                                                       float* __restrict__ out)
{
  extern __shared__ ull dsm[];                        // [sM 8*256 | sK 8*128 | sN 8*64]
  ull* sM = dsm;
  ull* sK = dsm + LCH*256;
  ull* sN = dsm + LCH*256 + LCH*128;
  const int c  = blockIdx.y;
  const bool trans = (c==0);
  const int nset = trans ? LCH : 1;
  for (int idx=threadIdx.x; idx<nset*256; idx+=TPB){
    int i=idx>>8, e=idx&255; int kk = trans ? i : (RS-1);
    sM[idx]=fdup(g_M[kk*256+e]);
  }
  for (int idx=threadIdx.x; idx<nset*128; idx+=TPB){
    int i=idx>>7, e=idx&127; int kk = trans ? i : (RS-1);
    sK[idx]=fdup(g_Kg[kk*128+e]);
  }
  for (int idx=threadIdx.x; idx<nset*64; idx+=TPB){
    int i=idx>>6, e=idx&63; int kk = trans ? i : (RS-1);
    sN[idx]=fdup(g_Ng[kk*64+e]);
  }
  const int b0 = (blockIdx.x*TPB + threadIdx.x)*NB;
  const int k0 = c*LCH;
  ull xp[SDIM];
  #pragma unroll
  for (int s=0;s<SDIM;s++)
    xp[s] = *(const ull*)&g_xs[((size_t)(c*SDIM+s))*BATCH + b0];
  __syncthreads();

  const float* ob0 = obs + ((size_t)b0*T_SEQ + k0)*ODIM;
  const float* ob1 = ob0 + (size_t)T_SEQ*ODIM;
  const float* uu0 = u   + ((size_t)b0*T_SEQ + k0)*IDIM;
  const float* uu1 = uu0 + (size_t)T_SEQ*IDIM;

  for (int i=0;i<LCH;i++){
    const int mi = trans ? i : 0;
    float4 z0a = *(const float4*)(ob0 + i*ODIM);
    float4 z0b = *(const float4*)(ob0 + i*ODIM + 4);
    float4 z1a = *(const float4*)(ob1 + i*ODIM);
    float4 z1b = *(const float4*)(ob1 + i*ODIM + 4);
    float4 v0  = *(const float4*)(uu0 + i*IDIM);
    float4 v1  = *(const float4*)(uu1 + i*IDIM);
    ull zp[8], up[4];
    zp[0]=fpair(z0a.x,z1a.x); zp[1]=fpair(z0a.y,z1a.y);
    zp[2]=fpair(z0a.z,z1a.z); zp[3]=fpair(z0a.w,z1a.w);
    zp[4]=fpair(z0b.x,z1b.x); zp[5]=fpair(z0b.y,z1b.y);
    zp[6]=fpair(z0b.z,z1b.z); zp[7]=fpair(z0b.w,z1b.w);
    up[0]=fpair(v0.x,v1.x);   up[1]=fpair(v0.y,v1.y);
    up[2]=fpair(v0.z,v1.z);   up[3]=fpair(v0.w,v1.w);

    const ulonglong2* M2 = (const ulonglong2*)&sM[mi*256];
    const ulonglong2* K2 = (const ulonglong2*)&sK[mi*128];
    const ulonglong2* N2 = (const ulonglong2*)&sN[mi*64];
    ull acc[SDIM];
    #pragma unroll
    for (int s=0;s<SDIM;s++){
      ulonglong2 k0p = K2[s*4+0];
      ull a = 0ull;
      ffma2(a, k0p.x, zp[0]); ffma2(a, k0p.y, zp[1]);
      ulonglong2 k1p = K2[s*4+1]; ffma2(a, k1p.x, zp[2]); ffma2(a, k1p.y, zp[3]);
      ulonglong2 k2p = K2[s*4+2]; ffma2(a, k2p.x, zp[4]); ffma2(a, k2p.y, zp[5]);
      ulonglong2 k3p = K2[s*4+3]; ffma2(a, k3p.x, zp[6]); ffma2(a, k3p.y, zp[7]);
      ulonglong2 n0p = N2[s*2+0]; ffma2(a, n0p.x, up[0]); ffma2(a, n0p.y, up[1]);
      ulonglong2 n1p = N2[s*2+1]; ffma2(a, n1p.x, up[2]); ffma2(a, n1p.y, up[3]);
      acc[s]=a;
    }
    #pragma unroll
    for (int s=0;s<SDIM;s++){
      ull a = acc[s];
      #pragma unroll
      for (int jj=0;jj<8;jj++){
        ulonglong2 mm = M2[s*8+jj];
        ffma2(a, mm.x, xp[2*jj]);
        ffma2(a, mm.y, xp[2*jj+1]);
      }
      acc[s]=a;
    }
    #pragma unroll
    for (int s=0;s<SDIM;s++) xp[s]=acc[s];

    {
      float a0[SDIM], a1[SDIM];
      #pragma unroll
      for (int s=0;s<SDIM;s++) unpack2(xp[s], a0[s], a1[s]);
      float4* o0 = (float4*)(out + (((size_t)b0*T_SEQ) + (size_t)(k0+i))*SDIM);
      float4* o1 = (float4*)(out + (((size_t)(b0+1)*T_SEQ) + (size_t)(k0+i))*SDIM);
      o0[0]=make_float4(a0[0],a0[1],a0[2],a0[3]);
      o0[1]=make_float4(a0[4],a0[5],a0[6],a0[7]);
      o0[2]=make_float4(a0[8],a0[9],a0[10],a0[11]);
      o0[3]=make_float4(a0[12],a0[13],a0[14],a0[15]);
      o1[0]=make_float4(a1[0],a1[1],a1[2],a1[3]);
      o1[1]=make_float4(a1[4],a1[5],a1[6],a1[7]);
      o1[2]=make_float4(a1[8],a1[9],a1[10],a1[11]);
      o1[3]=make_float4(a1[12],a1[13],a1[14],a1[15]);
    }
  }
}

extern "C" void kernel_launch(void* const* d_in, const int* in_sizes, int n_in,
                              void* d_out, int out_size)
{
  const float* obs = (const float*)d_in[0];
  const float* u   = (const float*)d_in[1];
  const float* A   = (const float*)d_in[2];
  const float* B   = (const float*)d_in[3];
  const float* C   = (const float*)d_in[4];
  const float* Q   = (const float*)d_in[5];
  const float* R   = (const float*)d_in[6];
  const float* x0  = (const float*)d_in[7];
  float* out = (float*)d_out;

  prep_kernel<<<1 + NT_Z + NT_U, 256>>>(A, B, C, Q, R, obs, u);

  dim3 gridR(BATCH/(TPB*NB), CH);
  resp_kernel<<<gridR, TPB>>>();
  pass2_kernel<<<BATCH/TPB, TPB>>>(x0);

  const int dynsmem = (LCH*256 + LCH*128 + LCH*64) * (int)sizeof(ull); // 28672
  pass3_kernel<<<gridR, TPB, dynsmem>>>(obs, u, out);
}

// round 12
// speedup vs baseline: 1.0924x; 1.0924x over previous
#include <cuda_runtime.h>
#include <cstdint>
#include <cstddef>

#define BATCH 4096
#define T_SEQ 512
#define SDIM  16
#define ODIM  8
#define IDIM  4
#define RS    8
#define CH    64
#define LCH   8
#define NB    2
#define TPB   128
#define NTYPE 2

typedef unsigned long long ull;

__device__ float g_M [RS*256];
__device__ float g_Kg[RS*128];
__device__ float g_Ng[RS*64];
__device__ float g_Phi[NTYPE*256];
__device__ float g_W  [NTYPE*16*96];            // [type][s][j*12 + q] (q: 0..7 z, 8..11 u)
__device__ float g_d [(size_t)CH*SDIM*BATCH];   // [c][s][b]
__device__ float g_xs[(size_t)CH*SDIM*BATCH];   // [c][s][b]
__device__ float g_tz[(size_t)T_SEQ*ODIM*BATCH]; // obs transposed [k][q][b]
__device__ float g_tu[(size_t)T_SEQ*IDIM*BATCH]; // u transposed [k][i][b]

// ---------- f32x2 helpers ----------
__device__ __forceinline__ ull fpair(float a, float b){
  ull r; asm("mov.b64 %0, {%1,%2};" : "=l"(r) : "f"(a), "f"(b)); return r;
}
__device__ __forceinline__ ull fdup(float a){ return fpair(a,a); }
__device__ __forceinline__ void ffma2(ull& d, ull a, ull b){
  asm("fma.rn.f32x2 %0, %1, %2, %0;" : "+l"(d) : "l"(a), "l"(b));
}

// Generic 32x32 tiled transpose: in (R x C) row-major -> out (C x R).
__global__ void __launch_bounds__(256) transpose_kernel(const float* __restrict__ in,
                                                        float* __restrict__ out,
                                                        int R, int C)
{
  __shared__ float tile[32][33];
  int c  = blockIdx.x*32 + threadIdx.x;
  int r0 = blockIdx.y*32;
  #pragma unroll
  for (int j=0;j<32;j+=8)
    tile[threadIdx.y+j][threadIdx.x] = in[(size_t)(r0+threadIdx.y+j)*C + c];
  __syncthreads();
  int r  = r0 + threadIdx.x;
  int c0 = blockIdx.x*32;
  #pragma unroll
  for (int j=0;j<32;j+=8)
    out[(size_t)(c0+threadIdx.y+j)*R + r] = tile[threadIdx.x][threadIdx.y+j];
}

// K1: Riccati (8 exact steps, Gauss-Jordan S-inverse) + W/Phi composition. 1 block, 256 thr.
__global__ void riccati_kernel(const float* __restrict__ A_, const float* __restrict__ B_,
                               const float* __restrict__ C_, const float* __restrict__ Q_,
                               const float* __restrict__ R_)
{
  __shared__ float sA[256], sQ[256], sC[128], sB[64], sR[64], sCA[128], sCB[32];
  __shared__ float P[256], Tm[256], Pp[256], CP[128], S8[64], Inv8[64], KK[128];
  __shared__ float BufA[256], BufB[256];
  __shared__ float sMh[RS*256], sKh[RS*128], sNh[RS*64];   // mirrors for composition
  const int t = threadIdx.x;
  const int s = t>>4, j = t&15;

  sA[t]=A_[t]; sQ[t]=Q_[t];
  P[t] = (s==j)?1.f:0.f;
  if (t<128) sC[t]=C_[t];
  if (t<64){ sB[t]=B_[t]; sR[t]=R_[t]; }
  __syncthreads();
  if (t<128){ int o=t>>4, jj=t&15; float a=0.f;
    #pragma unroll
    for(int m=0;m<16;m++) a+=sC[o*16+m]*sA[m*16+jj];
    sCA[t]=a; }
  if (t<32){ int o=t>>2, ii=t&3; float a=0.f;
    #pragma unroll
    for(int m=0;m<16;m++) a+=sC[o*16+m]*sB[m*4+ii];
    sCB[t]=a; }
  __syncthreads();

  for (int k=0;k<RS;k++){
    { float a=0.f;                                    // Tm = A @ P
      #pragma unroll
      for(int m=0;m<16;m++) a+=sA[s*16+m]*P[m*16+j];
      Tm[t]=a; }
    __syncthreads();
    { float a=sQ[t];                                  // Pp = Tm A^T + Q
      #pragma unroll
      for(int m=0;m<16;m++) a+=Tm[s*16+m]*sA[j*16+m];
      Pp[t]=a; }
    __syncthreads();
    if (t<128){ int o=t>>4, jj=t&15; float a=0.f;     // CP = C @ Pp
      #pragma unroll
      for(int m=0;m<16;m++) a+=sC[o*16+m]*Pp[m*16+jj];
      CP[t]=a; }
    __syncthreads();
    if (t<64){ int o=t>>3, p=t&7; float a=sR[t];      // S = CP C^T + R
      #pragma unroll
      for(int m=0;m<16;m++) a+=CP[o*16+m]*sC[p*16+m];
      S8[t]=a;
      Inv8[t]=(o==p)?1.f:0.f; }
    __syncthreads();
    // --- Gauss-Jordan inverse of S8 (SPD; no pivoting). threads t<64: (r,c)=(t>>3,t&7).
    for (int p=0;p<8;p++){
      if (t<64 && (t>>3)==p){                         // scale pivot row (single warp: lockstep-safe)
        float rp = 1.f/S8[p*8+p];
        S8[t]*=rp; Inv8[t]*=rp;
      }
      __syncthreads();
      float f=0.f, spc=0.f, sic=0.f, so=0.f, io=0.f;
      if (t<64){ int r=t>>3, cc=t&7;
        f=S8[r*8+p]; spc=S8[p*8+cc]; sic=Inv8[p*8+cc]; so=S8[t]; io=Inv8[t]; }
      __syncthreads();
      if (t<64 && (t>>3)!=p){
        S8[t]=so-f*spc; Inv8[t]=io-f*sic;
      }
      __syncthreads();
    }
    if (t<128){ int ss=t>>3, o=t&7; float a=0.f;      // K = CP^T Sinv
      #pragma unroll
      for(int p=0;p<8;p++) a+=CP[p*16+ss]*Inv8[p*8+o];
      KK[t]=a; }
    __syncthreads();
    { float a=Pp[t], mg=sA[t];                        // P_post, M_k
      #pragma unroll
      for(int o=0;o<8;o++){ float kv=KK[s*8+o]; a-=kv*CP[o*16+j]; mg-=kv*sCA[o*16+j]; }
      P[t]=a;
      sMh[k*256+t]=mg; g_M[k*256+t]=mg; }
    if (t<128){ sKh[k*128+t]=KK[t]; g_Kg[k*128+t]=KK[t]; }
    if (t<64){ int ss=t>>2, ii=t&3; float a=sB[t];    // N_k
      #pragma unroll
      for(int o=0;o<8;o++) a-=KK[ss*8+o]*sCB[o*4+ii];
      sNh[k*64+t]=a; g_Ng[k*64+t]=a; }
    __syncthreads();
  }

  // Per chunk type tt: suffix products; Wz_j=S_j K_j, Wu_j=S_j N_j; Phi = full product
  for (int tt=0; tt<NTYPE; tt++){
    float* Sb = BufA; float* Sn = BufB;
    Sb[t] = (s==j)?1.f:0.f;
    __syncthreads();
    for (int jj=LCH-1; jj>=0; jj--){
      const int k = (tt==0)? jj : (RS-1);
      if (t<128){ int ss=t>>3, o=t&7; float a=0.f;    // Wz
        #pragma unroll
        for(int m=0;m<16;m++) a+=Sb[ss*16+m]*sKh[k*128+m*8+o];
        g_W[(tt*16+ss)*96 + jj*12 + o] = a; }
      else { int e=t-128; int ss=e>>2, ii=e&3;        // Wu
        if (e<64){ float a=0.f;
          #pragma unroll
          for(int m=0;m<16;m++) a+=Sb[ss*16+m]*sNh[k*64+m*4+ii];
          g_W[(tt*16+ss)*96 + jj*12 + 8 + ii] = a; } }
      { float a=0.f;                                  // S = S @ M_k
        #pragma unroll
        for(int m=0;m<16;m++) a+=Sb[s*16+m]*sMh[k*256+m*16+j];
        Sn[t]=a; }
      __syncthreads();
      float* tmp=Sb; Sb=Sn; Sn=tmp;
    }
    g_Phi[tt*256+t]=Sb[t];
    __syncthreads();
  }
}

// P1: chunk response from zero state — d[c][:][b] = W(type) @ inputs(chunk c, batch b)
__global__ void __launch_bounds__(TPB) resp_kernel(void)
{
  __shared__ ull sW[16*96];                           // duplicated pairs, 12KB
  const int c  = blockIdx.y;
  const int tt = (c==0)?0:1;
  for (int idx=threadIdx.x; idx<16*96; idx+=TPB)
    sW[idx] = fdup(g_W[tt*16*96 + idx]);
  const int b0 = (blockIdx.x*TPB + threadIdx.x)*NB;
  const int k0 = c*LCH;
  ull acc[SDIM];
  #pragma unroll
  for (int s=0;s<SDIM;s++) acc[s]=0ull;
  __syncthreads();

  for (int jj=0;jj<LCH;jj++){
    ull ip[12];
    #pragma unroll
    for (int q=0;q<8;q++)
      ip[q] = *(const ull*)&g_tz[((size_t)(k0+jj)*8+q)*BATCH + b0];
    #pragma unroll
    for (int q=0;q<4;q++)
      ip[8+q] = *(const ull*)&g_tu[((size_t)(k0+jj)*4+q)*BATCH + b0];
    #pragma unroll
    for (int s=0;s<SDIM;s++){
      const ulonglong2* Wr = (const ulonglong2*)&sW[s*96 + jj*12];
      ull a = acc[s];
      #pragma unroll
      for (int q=0;q<6;q++){
        ulonglong2 w = Wr[q];
        ffma2(a, w.x, ip[2*q]);
        ffma2(a, w.y, ip[2*q+1]);
      }
      acc[s]=a;
    }
  }
  #pragma unroll
  for (int s=0;s<SDIM;s++)
    *(ull*)&g_d[((size_t)(c*SDIM+s))*BATCH + b0] = acc[s];
}

// P2: exact serial combine across chunks, one thread per batch.
__global__ void __launch_bounds__(TPB) pass2_kernel(const float* __restrict__ x0)
{
  __shared__ float sPhi[NTYPE*256];
  for (int e=threadIdx.x; e<NTYPE*256; e+=TPB) sPhi[e]=g_Phi[e];
  const int b = blockIdx.x*TPB + threadIdx.x;
  float x[16];
  #pragma unroll
  for(int s=0;s<16;s++) x[s]=x0[s];
  __syncthreads();
  #pragma unroll
  for(int s=0;s<16;s++) g_xs[(size_t)s*BATCH + b]=x[s];
  for (int c=1;c<CH;c++){
    int pidx = (c-1==0)?0:1;
    const float* Phi=&sPhi[pidx*256];
    float dd[16];
    #pragma unroll
    for(int s=0;s<16;s++) dd[s]=g_d[((size_t)((c-1)*16+s))*BATCH + b];
    float xn[16];
    #pragma unroll
    for(int s=0;s<16;s++){
      float a=dd[s];
      #pragma unroll
      for(int jj=0;jj<16;jj++) a+=Phi[s*16+jj]*x[jj];
      xn[s]=a;
    }
    #pragma unroll
    for(int s=0;s<16;s++) x[s]=xn[s];
    #pragma unroll
    for(int s=0;s<16;s++) g_xs[((size_t)(c*16+s))*BATCH + b]=x[s];
  }
}

// P3: serial recurrence within chunk; transposed coalesced loads + smem-staged stores.
#define SOUT_LD 258
__global__ void __launch_bounds__(TPB, 4) pass3_kernel(float* __restrict__ out)
{
  __shared__ ull sM[LCH*256], sK[LCH*128], sN[LCH*64];  // 28KB
  __shared__ float sOut[16*SOUT_LD];                    // 16.1KB staging
  const int tid = threadIdx.x;
  const int c  = blockIdx.y;
  const bool trans = (c==0);
  const int nset = trans ? LCH : 1;
  for (int idx=tid; idx<nset*256; idx+=TPB){
    int i=idx>>8, e=idx&255; int kk = trans ? i : (RS-1);
    sM[idx]=fdup(g_M[kk*256+e]);
  }
  for (int idx=tid; idx<nset*128; idx+=TPB){
    int i=idx>>7, e=idx&127; int kk = trans ? i : (RS-1);
    sK[idx]=fdup(g_Kg[kk*128+e]);
  }
  for (int idx=tid; idx<nset*64; idx+=TPB){
    int i=idx>>6, e=idx&63; int kk = trans ? i : (RS-1);
    sN[idx]=fdup(g_Ng[kk*64+e]);
  }
  const int b0 = blockIdx.x*(TPB*NB) + tid*NB;
  const int k0 = c*LCH;
  ull xp[SDIM];
  #pragma unroll
  for (int s=0;s<SDIM;s++)
    xp[s] = *(const ull*)&g_xs[((size_t)(c*SDIM+s))*BATCH + b0];
  __syncthreads();

  const int q  = tid & 3;        // output-store lane role
  const int bg = tid >> 2;

  for (int i=0;i<LCH;i++){
    const int mi = trans ? i : 0;
    ull zp[8], up[4];
    #pragma unroll
    for (int qq=0;qq<8;qq++)
      zp[qq] = *(const ull*)&g_tz[((size_t)(k0+i)*8+qq)*BATCH + b0];
    #pragma unroll
    for (int qq=0;qq<4;qq++)
      up[qq] = *(const ull*)&g_tu[((size_t)(k0+i)*4+qq)*BATCH + b0];

    const ulonglong2* M2 = (const ulonglong2*)&sM[mi*256];
    const ulonglong2* K2 = (const ulonglong2*)&sK[mi*128];
    const ulonglong2* N2 = (const ulonglong2*)&sN[mi*64];
    ull acc[SDIM];
    #pragma unroll
    for (int s=0;s<SDIM;s++){
      ulonglong2 k0p = K2[s*4+0];
      ull a = 0ull;
      ffma2(a, k0p.x, zp[0]); ffma2(a, k0p.y, zp[1]);
      ulonglong2 k1p = K2[s*4+1]; ffma2(a, k1p.x, zp[2]); ffma2(a, k1p.y, zp[3]);
      ulonglong2 k2p = K2[s*4+2]; ffma2(a, k2p.x, zp[4]); ffma2(a, k2p.y, zp[5]);
      ulonglong2 k3p = K2[s*4+3]; ffma2(a, k3p.x, zp[6]); ffma2(a, k3p.y, zp[7]);
      ulonglong2 n0p = N2[s*2+0]; ffma2(a, n0p.x, up[0]); ffma2(a, n0p.y, up[1]);
      ulonglong2 n1p = N2[s*2+1]; ffma2(a, n1p.x, up[2]); ffma2(a, n1p.y, up[3]);
      acc[s]=a;
    }
    #pragma unroll
    for (int s=0;s<SDIM;s++){
      ull a = acc[s];
      #pragma unroll
      for (int jj=0;jj<8;jj++){
        ulonglong2 mm = M2[s*8+jj];
        ffma2(a, mm.x, xp[2*jj]);
        ffma2(a, mm.y, xp[2*jj+1]);
      }
      acc[s]=a;
    }
    #pragma unroll
    for (int s=0;s<SDIM;s++) xp[s]=acc[s];

    // stage: sOut[s][local_batch] ; xp[s] packs (b0, b0+1)
    #pragma unroll
    for (int s=0;s<SDIM;s++)
      *(ull*)&sOut[s*SOUT_LD + tid*2] = xp[s];
    __syncthreads();
    // coalesced-ish writeback: 4 lanes per batch cover its 64B segment
    #pragma unroll
    for (int w=0;w<8;w++){
      int bl = bg + w*32;
      float4 v = make_float4(sOut[(q*4+0)*SOUT_LD + bl],
                             sOut[(q*4+1)*SOUT_LD + bl],
                             sOut[(q*4+2)*SOUT_LD + bl],
                             sOut[(q*4+3)*SOUT_LD + bl]);
      int gb = blockIdx.x*(TPB*NB) + bl;
      *(float4*)(out + ((size_t)gb*T_SEQ + (size_t)(k0+i))*SDIM + q*4) = v;
    }
    __syncthreads();
  }
}

extern "C" void kernel_launch(void* const* d_in, const int* in_sizes, int n_in,
                              void* d_out, int out_size)
{
  const float* obs = (const float*)d_in[0];
  const float* u   = (const float*)d_in[1];
  const float* A   = (const float*)d_in[2];
  const float* B   = (const float*)d_in[3];
  const float* C   = (const float*)d_in[4];
  const float* Q   = (const float*)d_in[5];
  const float* R   = (const float*)d_in[6];
  const float* x0  = (const float*)d_in[7];
  float* out = (float*)d_out;

  riccati_kernel<<<1, 256>>>(A, B, C, Q, R);

  float* tz; cudaGetSymbolAddress((void**)&tz, g_tz);
  float* tu; cudaGetSymbolAddress((void**)&tu, g_tu);
  dim3 tb(32,8);
  transpose_kernel<<<dim3((T_SEQ*ODIM)/32, BATCH/32), tb>>>(obs, tz, BATCH, T_SEQ*ODIM);
  transpose_kernel<<<dim3((T_SEQ*IDIM)/32, BATCH/32), tb>>>(u,   tu, BATCH, T_SEQ*IDIM);

  dim3 gridR(BATCH/(TPB*NB), CH);
  resp_kernel<<<gridR, TPB>>>();
  pass2_kernel<<<BATCH/TPB, TPB>>>(x0);
  pass3_kernel<<<gridR, TPB>>>(out);
}

// round 13
// speedup vs baseline: 1.1272x; 1.0318x over previous
#include <cuda_runtime.h>
#include <cstdint>
#include <cstddef>

#define BATCH 4096
#define T_SEQ 512
#define SDIM  16
#define ODIM  8
#define IDIM  4
#define RS    8
#define CH    64
#define LCH   8
#define NB    2
#define TPB   128
#define NTYPE 2

typedef unsigned long long ull;

__device__ float g_M [RS*256];
__device__ float g_Kg[RS*128];
__device__ float g_Ng[RS*64];
__device__ float g_Phi[NTYPE*256];
__device__ float g_W  [NTYPE*16*96];            // [type][s][j*12 + q] (q: 0..7 z, 8..11 u)
__device__ float g_d [(size_t)CH*SDIM*BATCH];   // [c][s][b]
__device__ float g_xs[(size_t)CH*SDIM*BATCH];   // [c][s][b]

// ---------- f32x2 helpers ----------
__device__ __forceinline__ ull fpair(float a, float b){
  ull r; asm("mov.b64 %0, {%1,%2};" : "=l"(r) : "f"(a), "f"(b)); return r;
}
__device__ __forceinline__ ull fdup(float a){ return fpair(a,a); }
__device__ __forceinline__ void ffma2(ull& d, ull a, ull b){
  asm("fma.rn.f32x2 %0, %1, %2, %0;" : "+l"(d) : "l"(a), "l"(b));
}

// K1: Riccati (8 exact steps, Gauss-Jordan S-inverse) + W/Phi composition. 1 block, 256 thr.
__global__ void riccati_kernel(const float* __restrict__ A_, const float* __restrict__ B_,
                               const float* __restrict__ C_, const float* __restrict__ Q_,
                               const float* __restrict__ R_)
{
  __shared__ float sA[256], sQ[256], sC[128], sB[64], sR[64], sCA[128], sCB[32];
  __shared__ float P[256], Tm[256], Pp[256], CP[128], S8[64], Inv8[64], KK[128];
  __shared__ float BufA[256], BufB[256];
  __shared__ float sMh[RS*256], sKh[RS*128], sNh[RS*64];   // mirrors for composition
  const int t = threadIdx.x;
  const int s = t>>4, j = t&15;

  sA[t]=A_[t]; sQ[t]=Q_[t];
  P[t] = (s==j)?1.f:0.f;
  if (t<128) sC[t]=C_[t];
  if (t<64){ sB[t]=B_[t]; sR[t]=R_[t]; }
  __syncthreads();
  if (t<128){ int o=t>>4, jj=t&15; float a=0.f;
    #pragma unroll
    for(int m=0;m<16;m++) a+=sC[o*16+m]*sA[m*16+jj];
    sCA[t]=a; }
  if (t<32){ int o=t>>2, ii=t&3; float a=0.f;
    #pragma unroll
    for(int m=0;m<16;m++) a+=sC[o*16+m]*sB[m*4+ii];
    sCB[t]=a; }
  __syncthreads();

  for (int k=0;k<RS;k++){
    { float a=0.f;                                    // Tm = A @ P
      #pragma unroll
      for(int m=0;m<16;m++) a+=sA[s*16+m]*P[m*16+j];
      Tm[t]=a; }
    __syncthreads();
    { float a=sQ[t];                                  // Pp = Tm A^T + Q
      #pragma unroll
      for(int m=0;m<16;m++) a+=Tm[s*16+m]*sA[j*16+m];
      Pp[t]=a; }
    __syncthreads();
    if (t<128){ int o=t>>4, jj=t&15; float a=0.f;     // CP = C @ Pp
      #pragma unroll
      for(int m=0;m<16;m++) a+=sC[o*16+m]*Pp[m*16+jj];
      CP[t]=a; }
    __syncthreads();
    if (t<64){ int o=t>>3, p=t&7; float a=sR[t];      // S = CP C^T + R
      #pragma unroll
      for(int m=0;m<16;m++) a+=CP[o*16+m]*sC[p*16+m];
      S8[t]=a;
      Inv8[t]=(o==p)?1.f:0.f; }
    __syncthreads();
    // --- Gauss-Jordan inverse of S8 (SPD; no pivoting). threads t<64: (r,c)=(t>>3,t&7).
    for (int p=0;p<8;p++){
      if (t<64 && (t>>3)==p){
        float rp = 1.f/S8[p*8+p];
        S8[t]*=rp; Inv8[t]*=rp;
      }
      __syncthreads();
      float f=0.f, spc=0.f, sic=0.f, so=0.f, io=0.f;
      if (t<64){
        f=S8[(t>>3)*8+p]; spc=S8[p*8+(t&7)]; sic=Inv8[p*8+(t&7)]; so=S8[t]; io=Inv8[t]; }
      __syncthreads();
      if (t<64 && (t>>3)!=p){
        S8[t]=so-f*spc; Inv8[t]=io-f*sic;
      }
      __syncthreads();
    }
    if (t<128){ int ss=t>>3, o=t&7; float a=0.f;      // K = CP^T Sinv
      #pragma unroll
      for(int p=0;p<8;p++) a+=CP[p*16+ss]*Inv8[p*8+o];
      KK[t]=a; }
    __syncthreads();
    { float a=Pp[t], mg=sA[t];                        // P_post, M_k
      #pragma unroll
      for(int o=0;o<8;o++){ float kv=KK[s*8+o]; a-=kv*CP[o*16+j]; mg-=kv*sCA[o*16+j]; }
      P[t]=a;
      sMh[k*256+t]=mg; g_M[k*256+t]=mg; }
    if (t<128){ sKh[k*128+t]=KK[t]; g_Kg[k*128+t]=KK[t]; }
    if (t<64){ int ss=t>>2, ii=t&3; float a=sB[t];    // N_k
      #pragma unroll
      for(int o=0;o<8;o++) a-=KK[ss*8+o]*sCB[o*4+ii];
      sNh[k*64+t]=a; g_Ng[k*64+t]=a; }
    __syncthreads();
  }

  // Per chunk type tt: suffix products; Wz_j=S_j K_j, Wu_j=S_j N_j; Phi = full product
  for (int tt=0; tt<NTYPE; tt++){
    float* Sb = BufA; float* Sn = BufB;
    Sb[t] = (s==j)?1.f:0.f;
    __syncthreads();
    for (int jj=LCH-1; jj>=0; jj--){
      const int k = (tt==0)? jj : (RS-1);
      if (t<128){ int ss=t>>3, o=t&7; float a=0.f;    // Wz
        #pragma unroll
        for(int m=0;m<16;m++) a+=Sb[ss*16+m]*sKh[k*128+m*8+o];
        g_W[(tt*16+ss)*96 + jj*12 + o] = a; }
      else { int e=t-128; int ss=e>>2, ii=e&3;        // Wu
        if (e<64){ float a=0.f;
          #pragma unroll
          for(int m=0;m<16;m++) a+=Sb[ss*16+m]*sNh[k*64+m*4+ii];
          g_W[(tt*16+ss)*96 + jj*12 + 8 + ii] = a; } }
      { float a=0.f;                                  // S = S @ M_k
        #pragma unroll
        for(int m=0;m<16;m++) a+=Sb[s*16+m]*sMh[k*256+m*16+j];
        Sn[t]=a; }
      __syncthreads();
      float* tmp=Sb; Sb=Sn; Sn=tmp;
    }
    g_Phi[tt*256+t]=Sb[t];
    __syncthreads();
  }
}

// P1 (R9 body): chunk response from zero state, gathered input loads.
__global__ void __launch_bounds__(TPB) resp_kernel(const float* __restrict__ obs,
                                                   const float* __restrict__ u)
{
  __shared__ ull sW[16*96];                           // duplicated pairs, 12KB
  const int c  = blockIdx.y;
  const int tt = (c==0)?0:1;
  for (int idx=threadIdx.x; idx<16*96; idx+=TPB)
    sW[idx] = fdup(g_W[tt*16*96 + idx]);
  const int b0 = (blockIdx.x*TPB + threadIdx.x)*NB;
  const int k0 = c*LCH;
  ull acc[SDIM];
  #pragma unroll
  for (int s=0;s<SDIM;s++) acc[s]=0ull;
  __syncthreads();

  const float* ob0 = obs + ((size_t)b0*T_SEQ + k0)*ODIM;
  const float* ob1 = ob0 + (size_t)T_SEQ*ODIM;
  const float* uu0 = u   + ((size_t)b0*T_SEQ + k0)*IDIM;
  const float* uu1 = uu0 + (size_t)T_SEQ*IDIM;

  for (int jj=0;jj<LCH;jj++){
    float4 z0a = *(const float4*)(ob0 + jj*ODIM);
    float4 z0b = *(const float4*)(ob0 + jj*ODIM + 4);
    float4 z1a = *(const float4*)(ob1 + jj*ODIM);
    float4 z1b = *(const float4*)(ob1 + jj*ODIM + 4);
    float4 v0  = *(const float4*)(uu0 + jj*IDIM);
    float4 v1  = *(const float4*)(uu1 + jj*IDIM);
    ull ip[12];
    ip[0]=fpair(z0a.x,z1a.x); ip[1]=fpair(z0a.y,z1a.y);
    ip[2]=fpair(z0a.z,z1a.z); ip[3]=fpair(z0a.w,z1a.w);
    ip[4]=fpair(z0b.x,z1b.x); ip[5]=fpair(z0b.y,z1b.y);
    ip[6]=fpair(z0b.z,z1b.z); ip[7]=fpair(z0b.w,z1b.w);
    ip[8]=fpair(v0.x,v1.x);   ip[9]=fpair(v0.y,v1.y);
    ip[10]=fpair(v0.z,v1.z);  ip[11]=fpair(v0.w,v1.w);
    #pragma unroll
    for (int s=0;s<SDIM;s++){
      const ulonglong2* Wr = (const ulonglong2*)&sW[s*96 + jj*12];
      ull a = acc[s];
      #pragma unroll
      for (int q=0;q<6;q++){
        ulonglong2 w = Wr[q];
        ffma2(a, w.x, ip[2*q]);
        ffma2(a, w.y, ip[2*q+1]);
      }
      acc[s]=a;
    }
  }
  #pragma unroll
  for (int s=0;s<SDIM;s++)
    *(ull*)&g_d[((size_t)(c*SDIM+s))*BATCH + b0] = acc[s];
}

// P2: exact serial combine across chunks, one thread per batch.
__global__ void __launch_bounds__(TPB) pass2_kernel(const float* __restrict__ x0)
{
  __shared__ float sPhi[NTYPE*256];
  for (int e=threadIdx.x; e<NTYPE*256; e+=TPB) sPhi[e]=g_Phi[e];
  const int b = blockIdx.x*TPB + threadIdx.x;
  float x[16];
  #pragma unroll
  for(int s=0;s<16;s++) x[s]=x0[s];
  __syncthreads();
  #pragma unroll
  for(int s=0;s<16;s++) g_xs[(size_t)s*BATCH + b]=x[s];
  for (int c=1;c<CH;c++){
    int pidx = (c-1==0)?0:1;
    const float* Phi=&sPhi[pidx*256];
    float dd[16];
    #pragma unroll
    for(int s=0;s<16;s++) dd[s]=g_d[((size_t)((c-1)*16+s))*BATCH + b];
    float xn[16];
    #pragma unroll
    for(int s=0;s<16;s++){
      float a=dd[s];
      #pragma unroll
      for(int jj=0;jj<16;jj++) a+=Phi[s*16+jj]*x[jj];
      xn[s]=a;
    }
    #pragma unroll
    for(int s=0;s<16;s++) x[s]=xn[s];
    #pragma unroll
    for(int s=0;s<16;s++) g_xs[((size_t)(c*16+s))*BATCH + b]=x[s];
  }
}

// P3: R9 gather-input body + smem-staged coalesced stores.
#define SOUT_LD 258
__global__ void __launch_bounds__(TPB, 4) pass3_kernel(const float* __restrict__ obs,
                                                       const float* __restrict__ u,
                                                       float* __restrict__ out)
{
  __shared__ ull sM[LCH*256], sK[LCH*128], sN[LCH*64];  // 28KB
  __shared__ float sOut[16*SOUT_LD];                    // 16.1KB staging
  const int tid = threadIdx.x;
  const int c  = blockIdx.y;
  const bool trans = (c==0);
  const int nset = trans ? LCH : 1;
  for (int idx=tid; idx<nset*256; idx+=TPB){
    int i=idx>>8, e=idx&255; int kk = trans ? i : (RS-1);
    sM[idx]=fdup(g_M[kk*256+e]);
  }
  for (int idx=tid; idx<nset*128; idx+=TPB){
    int i=idx>>7, e=idx&127; int kk = trans ? i : (RS-1);
    sK[idx]=fdup(g_Kg[kk*128+e]);
  }
  for (int idx=tid; idx<nset*64; idx+=TPB){
    int i=idx>>6, e=idx&63; int kk = trans ? i : (RS-1);
    sN[idx]=fdup(g_Ng[kk*64+e]);
  }
  const int b0 = blockIdx.x*(TPB*NB) + tid*NB;
  const int k0 = c*LCH;
  ull xp[SDIM];
  #pragma unroll
  for (int s=0;s<SDIM;s++)
    xp[s] = *(const ull*)&g_xs[((size_t)(c*SDIM+s))*BATCH + b0];
  __syncthreads();

  const float* ob0 = obs + ((size_t)b0*T_SEQ + k0)*ODIM;
  const float* ob1 = ob0 + (size_t)T_SEQ*ODIM;
  const float* uu0 = u   + ((size_t)b0*T_SEQ + k0)*IDIM;
  const float* uu1 = uu0 + (size_t)T_SEQ*IDIM;

  const int q  = tid & 3;        // output-store lane role
  const int bg = tid >> 2;

  for (int i=0;i<LCH;i++){
    const int mi = trans ? i : 0;
    float4 z0a = *(const float4*)(ob0 + i*ODIM);
    float4 z0b = *(const float4*)(ob0 + i*ODIM + 4);
    float4 z1a = *(const float4*)(ob1 + i*ODIM);
    float4 z1b = *(const float4*)(ob1 + i*ODIM + 4);
    float4 v0  = *(const float4*)(uu0 + i*IDIM);
    float4 v1  = *(const float4*)(uu1 + i*IDIM);
    ull zp[8], up[4];
    zp[0]=fpair(z0a.x,z1a.x); zp[1]=fpair(z0a.y,z1a.y);
    zp[2]=fpair(z0a.z,z1a.z); zp[3]=fpair(z0a.w,z1a.w);
    zp[4]=fpair(z0b.x,z1b.x); zp[5]=fpair(z0b.y,z1b.y);
    zp[6]=fpair(z0b.z,z1b.z); zp[7]=fpair(z0b.w,z1b.w);
    up[0]=fpair(v0.x,v1.x);   up[1]=fpair(v0.y,v1.y);
    up[2]=fpair(v0.z,v1.z);   up[3]=fpair(v0.w,v1.w);

    const ulonglong2* M2 = (const ulonglong2*)&sM[mi*256];
    const ulonglong2* K2 = (const ulonglong2*)&sK[mi*128];
    const ulonglong2* N2 = (const ulonglong2*)&sN[mi*64];
    ull acc[SDIM];
    #pragma unroll
    for (int s=0;s<SDIM;s++){
      ulonglong2 k0p = K2[s*4+0];
      ull a = 0ull;
      ffma2(a, k0p.x, zp[0]); ffma2(a, k0p.y, zp[1]);
      ulonglong2 k1p = K2[s*4+1]; ffma2(a, k1p.x, zp[2]); ffma2(a, k1p.y, zp[3]);
      ulonglong2 k2p = K2[s*4+2]; ffma2(a, k2p.x, zp[4]); ffma2(a, k2p.y, zp[5]);
      ulonglong2 k3p = K2[s*4+3]; ffma2(a, k3p.x, zp[6]); ffma2(a, k3p.y, zp[7]);
      ulonglong2 n0p = N2[s*2+0]; ffma2(a, n0p.x, up[0]); ffma2(a, n0p.y, up[1]);
      ulonglong2 n1p = N2[s*2+1]; ffma2(a, n1p.x, up[2]); ffma2(a, n1p.y, up[3]);
      acc[s]=a;
    }
    #pragma unroll
    for (int s=0;s<SDIM;s++){
      ull a = acc[s];
      #pragma unroll
      for (int jj=0;jj<8;jj++){
        ulonglong2 mm = M2[s*8+jj];
        ffma2(a, mm.x, xp[2*jj]);
        ffma2(a, mm.y, xp[2*jj+1]);
      }
      acc[s]=a;
    }
    #pragma unroll
    for (int s=0;s<SDIM;s++) xp[s]=acc[s];

    // stage (conflict-free: stride 258 ≡ 2 mod 32), then coalesced writeback
    #pragma unroll
    for (int s=0;s<SDIM;s++)
      *(ull*)&sOut[s*SOUT_LD + tid*2] = xp[s];
    __syncthreads();
    #pragma unroll
    for (int w=0;w<8;w++){
      int bl = bg + w*32;
      float4 v = make_float4(sOut[(q*4+0)*SOUT_LD + bl],
                             sOut[(q*4+1)*SOUT_LD + bl],
                             sOut[(q*4+2)*SOUT_LD + bl],
                             sOut[(q*4+3)*SOUT_LD + bl]);
      int gb = blockIdx.x*(TPB*NB) + bl;
      *(float4*)(out + ((size_t)gb*T_SEQ + (size_t)(k0+i))*SDIM + q*4) = v;
    }
    __syncthreads();
  }
}

extern "C" void kernel_launch(void* const* d_in, const int* in_sizes, int n_in,
                              void* d_out, int out_size)
{
  const float* obs = (const float*)d_in[0];
  const float* u   = (const float*)d_in[1];
  const float* A   = (const float*)d_in[2];
  const float* B   = (const float*)d_in[3];
  const float* C   = (const float*)d_in[4];
  const float* Q   = (const float*)d_in[5];
  const float* R   = (const float*)d_in[6];
  const float* x0  = (const float*)d_in[7];
  float* out = (float*)d_out;

  riccati_kernel<<<1, 256>>>(A, B, C, Q, R);

  dim3 gridR(BATCH/(TPB*NB), CH);
  resp_kernel<<<gridR, TPB>>>(obs, u);
  pass2_kernel<<<BATCH/TPB, TPB>>>(x0);
  pass3_kernel<<<gridR, TPB>>>(obs, u, out);
}

// round 14
// speedup vs baseline: 1.1468x; 1.0174x over previous
#include <cuda_runtime.h>
#include <cstdint>
#include <cstddef>

#define BATCH 4096
#define T_SEQ 512
#define SDIM  16
#define ODIM  8
#define IDIM  4
#define RS    8
#define CH    64
#define LCH   8
#define NB    2
#define TPB   128
#define NTYPE 2

typedef unsigned long long ull;

__device__ float g_M [RS*256];
__device__ float g_Kg[RS*128];
__device__ float g_Ng[RS*64];
__device__ float g_Phi[NTYPE*256];
__device__ float g_W  [NTYPE*16*96];            // [type][s][j*12 + q] (q: 0..7 z, 8..11 u)
__device__ float g_d [(size_t)CH*SDIM*BATCH];   // [c][s][b]
__device__ float g_xs[(size_t)CH*SDIM*BATCH];   // [c][s][b]

// ---------- f32x2 helpers ----------
__device__ __forceinline__ ull fpair(float a, float b){
  ull r; asm("mov.b64 %0, {%1,%2};" : "=l"(r) : "f"(a), "f"(b)); return r;
}
__device__ __forceinline__ ull fdup(float a){ return fpair(a,a); }
__device__ __forceinline__ void unpack2(ull p, float& a, float& b){
  asm("mov.b64 {%0,%1}, %2;" : "=f"(a), "=f"(b) : "l"(p));
}
__device__ __forceinline__ void ffma2(ull& d, ull a, ull b){
  asm("fma.rn.f32x2 %0, %1, %2, %0;" : "+l"(d) : "l"(a), "l"(b));
}

// ---------- 256-bit global memory ops (sm_100+) ----------
__device__ __forceinline__ void ldg256(float* r, const float* p){
  asm("ld.global.v8.f32 {%0,%1,%2,%3,%4,%5,%6,%7}, [%8];"
      : "=f"(r[0]),"=f"(r[1]),"=f"(r[2]),"=f"(r[3]),
        "=f"(r[4]),"=f"(r[5]),"=f"(r[6]),"=f"(r[7])
      : "l"(p));
}
__device__ __forceinline__ void stg256(float* p, const float* r){
  asm volatile("st.global.v8.f32 [%0], {%1,%2,%3,%4,%5,%6,%7,%8};"
      :: "l"(p),
         "f"(r[0]),"f"(r[1]),"f"(r[2]),"f"(r[3]),
         "f"(r[4]),"f"(r[5]),"f"(r[6]),"f"(r[7])
      : "memory");
}

// K1: Riccati (8 exact steps, Gauss-Jordan S-inverse) + W/Phi composition. 1 block, 256 thr.
__global__ void riccati_kernel(const float* __restrict__ A_, const float* __restrict__ B_,
                               const float* __restrict__ C_, const float* __restrict__ Q_,
                               const float* __restrict__ R_)
{
  __shared__ float sA[256], sQ[256], sC[128], sB[64], sR[64], sCA[128], sCB[32];
  __shared__ float P[256], Tm[256], Pp[256], CP[128], S8[64], Inv8[64], KK[128];
  __shared__ float BufA[256], BufB[256];
  __shared__ float sMh[RS*256], sKh[RS*128], sNh[RS*64];
  const int t = threadIdx.x;
  const int s = t>>4, j = t&15;

  sA[t]=A_[t]; sQ[t]=Q_[t];
  P[t] = (s==j)?1.f:0.f;
  if (t<128) sC[t]=C_[t];
  if (t<64){ sB[t]=B_[t]; sR[t]=R_[t]; }
  __syncthreads();
  if (t<128){ int o=t>>4, jj=t&15; float a=0.f;
    #pragma unroll
    for(int m=0;m<16;m++) a+=sC[o*16+m]*sA[m*16+jj];
    sCA[t]=a; }
  if (t<32){ int o=t>>2, ii=t&3; float a=0.f;
    #pragma unroll
    for(int m=0;m<16;m++) a+=sC[o*16+m]*sB[m*4+ii];
    sCB[t]=a; }
  __syncthreads();

  for (int k=0;k<RS;k++){
    { float a=0.f;                                    // Tm = A @ P
      #pragma unroll
      for(int m=0;m<16;m++) a+=sA[s*16+m]*P[m*16+j];
      Tm[t]=a; }
    __syncthreads();
    { float a=sQ[t];                                  // Pp = Tm A^T + Q
      #pragma unroll
      for(int m=0;m<16;m++) a+=Tm[s*16+m]*sA[j*16+m];
      Pp[t]=a; }
    __syncthreads();
    if (t<128){ int o=t>>4, jj=t&15; float a=0.f;     // CP = C @ Pp
      #pragma unroll
      for(int m=0;m<16;m++) a+=sC[o*16+m]*Pp[m*16+jj];
      CP[t]=a; }
    __syncthreads();
    if (t<64){ int o=t>>3, p=t&7; float a=sR[t];      // S = CP C^T + R
      #pragma unroll
      for(int m=0;m<16;m++) a+=CP[o*16+m]*sC[p*16+m];
      S8[t]=a;
      Inv8[t]=(o==p)?1.f:0.f; }
    __syncthreads();
    for (int p=0;p<8;p++){                            // Gauss-Jordan (SPD, no pivoting)
      if (t<64 && (t>>3)==p){
        float rp = 1.f/S8[p*8+p];
        S8[t]*=rp; Inv8[t]*=rp;
      }
      __syncthreads();
      float f=0.f, spc=0.f, sic=0.f, so=0.f, io=0.f;
      if (t<64){
        f=S8[(t>>3)*8+p]; spc=S8[p*8+(t&7)]; sic=Inv8[p*8+(t&7)]; so=S8[t]; io=Inv8[t]; }
      __syncthreads();
      if (t<64 && (t>>3)!=p){
        S8[t]=so-f*spc; Inv8[t]=io-f*sic;
      }
      __syncthreads();
    }
    if (t<128){ int ss=t>>3, o=t&7; float a=0.f;      // K = CP^T Sinv
      #pragma unroll
      for(int p=0;p<8;p++) a+=CP[p*16+ss]*Inv8[p*8+o];
      KK[t]=a; }
    __syncthreads();
    { float a=Pp[t], mg=sA[t];                        // P_post, M_k
      #pragma unroll
      for(int o=0;o<8;o++){ float kv=KK[s*8+o]; a-=kv*CP[o*16+j]; mg-=kv*sCA[o*16+j]; }
      P[t]=a;
      sMh[k*256+t]=mg; g_M[k*256+t]=mg; }
    if (t<128){ sKh[k*128+t]=KK[t]; g_Kg[k*128+t]=KK[t]; }
    if (t<64){ int ss=t>>2, ii=t&3; float a=sB[t];    // N_k
      #pragma unroll
      for(int o=0;o<8;o++) a-=KK[ss*8+o]*sCB[o*4+ii];
      sNh[k*64+t]=a; g_Ng[k*64+t]=a; }
    __syncthreads();
  }

  for (int tt=0; tt<NTYPE; tt++){                     // W + Phi per chunk type
    float* Sb = BufA; float* Sn = BufB;
    Sb[t] = (s==j)?1.f:0.f;
    __syncthreads();
    for (int jj=LCH-1; jj>=0; jj--){
      const int k = (tt==0)? jj : (RS-1);
      if (t<128){ int ss=t>>3, o=t&7; float a=0.f;    // Wz
        #pragma unroll
        for(int m=0;m<16;m++) a+=Sb[ss*16+m]*sKh[k*128+m*8+o];
        g_W[(tt*16+ss)*96 + jj*12 + o] = a; }
      else { int e=t-128; int ss=e>>2, ii=e&3;        // Wu
        if (e<64){ float a=0.f;
          #pragma unroll
          for(int m=0;m<16;m++) a+=Sb[ss*16+m]*sNh[k*64+m*4+ii];
          g_W[(tt*16+ss)*96 + jj*12 + 8 + ii] = a; } }
      { float a=0.f;                                  // S = S @ M_k
        #pragma unroll
        for(int m=0;m<16;m++) a+=Sb[s*16+m]*sMh[k*256+m*16+j];
        Sn[t]=a; }
      __syncthreads();
      float* tmp=Sb; Sb=Sn; Sn=tmp;
    }
    g_Phi[tt*256+t]=Sb[t];
    __syncthreads();
  }
}

// P1: chunk response from zero state; z via 256-bit loads.
__global__ void __launch_bounds__(TPB) resp_kernel(const float* __restrict__ obs,
                                                   const float* __restrict__ u)
{
  __shared__ ull sW[16*96];
  const int c  = blockIdx.y;
  const int tt = (c==0)?0:1;
  for (int idx=threadIdx.x; idx<16*96; idx+=TPB)
    sW[idx] = fdup(g_W[tt*16*96 + idx]);
  const int b0 = (blockIdx.x*TPB + threadIdx.x)*NB;
  const int k0 = c*LCH;
  ull acc[SDIM];
  #pragma unroll
  for (int s=0;s<SDIM;s++) acc[s]=0ull;
  __syncthreads();

  const float* ob0 = obs + ((size_t)b0*T_SEQ + k0)*ODIM;
  const float* ob1 = ob0 + (size_t)T_SEQ*ODIM;
  const float* uu0 = u   + ((size_t)b0*T_SEQ + k0)*IDIM;
  const float* uu1 = uu0 + (size_t)T_SEQ*IDIM;

  for (int jj=0;jj<LCH;jj++){
    float z0[8], z1[8];
    ldg256(z0, ob0 + jj*ODIM);
    ldg256(z1, ob1 + jj*ODIM);
    float4 v0  = *(const float4*)(uu0 + jj*IDIM);
    float4 v1  = *(const float4*)(uu1 + jj*IDIM);
    ull ip[12];
    #pragma unroll
    for (int q=0;q<8;q++) ip[q]=fpair(z0[q],z1[q]);
    ip[8]=fpair(v0.x,v1.x);   ip[9]=fpair(v0.y,v1.y);
    ip[10]=fpair(v0.z,v1.z);  ip[11]=fpair(v0.w,v1.w);
    #pragma unroll
    for (int s=0;s<SDIM;s++){
      const ulonglong2* Wr = (const ulonglong2*)&sW[s*96 + jj*12];
      ull a = acc[s];
      #pragma unroll
      for (int q=0;q<6;q++){
        ulonglong2 w = Wr[q];
        ffma2(a, w.x, ip[2*q]);
        ffma2(a, w.y, ip[2*q+1]);
      }
      acc[s]=a;
    }
  }
  #pragma unroll
  for (int s=0;s<SDIM;s++)
    *(ull*)&g_d[((size_t)(c*SDIM+s))*BATCH + b0] = acc[s];
}

// P2: exact serial combine across chunks, one thread per batch.
__global__ void __launch_bounds__(TPB) pass2_kernel(const float* __restrict__ x0)
{
  __shared__ float sPhi[NTYPE*256];
  for (int e=threadIdx.x; e<NTYPE*256; e+=TPB) sPhi[e]=g_Phi[e];
  const int b = blockIdx.x*TPB + threadIdx.x;
  float x[16];
  #pragma unroll
  for(int s=0;s<16;s++) x[s]=x0[s];
  __syncthreads();
  #pragma unroll
  for(int s=0;s<16;s++) g_xs[(size_t)s*BATCH + b]=x[s];
  for (int c=1;c<CH;c++){
    int pidx = (c-1==0)?0:1;
    const float* Phi=&sPhi[pidx*256];
    float dd[16];
    #pragma unroll
    for(int s=0;s<16;s++) dd[s]=g_d[((size_t)((c-1)*16+s))*BATCH + b];
    float xn[16];
    #pragma unroll
    for(int s=0;s<16;s++){
      float a=dd[s];
      #pragma unroll
      for(int jj=0;jj<16;jj++) a+=Phi[s*16+jj]*x[jj];
      xn[s]=a;
    }
    #pragma unroll
    for(int s=0;s<16;s++) x[s]=xn[s];
    #pragma unroll
    for(int s=0;s<16;s++) g_xs[((size_t)(c*16+s))*BATCH + b]=x[s];
  }
}

// P3: R9 body with 256-bit z loads + 256-bit output stores.
__global__ void __launch_bounds__(TPB, 4) pass3_kernel(const float* __restrict__ obs,
                                                       const float* __restrict__ u,
                                                       float* __restrict__ out)
{
  __shared__ ull sM[LCH*256], sK[LCH*128], sN[LCH*64];  // 28KB
  const int tid = threadIdx.x;
  const int c  = blockIdx.y;
  const bool trans = (c==0);
  const int nset = trans ? LCH : 1;
  for (int idx=tid; idx<nset*256; idx+=TPB){
    int i=idx>>8, e=idx&255; int kk = trans ? i : (RS-1);
    sM[idx]=fdup(g_M[kk*256+e]);
  }
  for (int idx=tid; idx<nset*128; idx+=TPB){
    int i=idx>>7, e=idx&127; int kk = trans ? i : (RS-1);
    sK[idx]=fdup(g_Kg[kk*128+e]);
  }
  for (int idx=tid; idx<nset*64; idx+=TPB){
    int i=idx>>6, e=idx&63; int kk = trans ? i : (RS-1);
    sN[idx]=fdup(g_Ng[kk*64+e]);
  }
  const int b0 = blockIdx.x*(TPB*NB) + tid*NB;
  const int k0 = c*LCH;
  ull xp[SDIM];
  #pragma unroll
  for (int s=0;s<SDIM;s++)
    xp[s] = *(const ull*)&g_xs[((size_t)(c*SDIM+s))*BATCH + b0];
  __syncthreads();

  const float* ob0 = obs + ((size_t)b0*T_SEQ + k0)*ODIM;
  const float* ob1 = ob0 + (size_t)T_SEQ*ODIM;
  const float* uu0 = u   + ((size_t)b0*T_SEQ + k0)*IDIM;
  const float* uu1 = uu0 + (size_t)T_SEQ*IDIM;

  for (int i=0;i<LCH;i++){
    const int mi = trans ? i : 0;
    float z0[8], z1[8];
    ldg256(z0, ob0 + i*ODIM);
    ldg256(z1, ob1 + i*ODIM);
    float4 v0  = *(const float4*)(uu0 + i*IDIM);
    float4 v1  = *(const float4*)(uu1 + i*IDIM);
    ull zp[8], up[4];
    #pragma unroll
    for (int q=0;q<8;q++) zp[q]=fpair(z0[q],z1[q]);
    up[0]=fpair(v0.x,v1.x);   up[1]=fpair(v0.y,v1.y);
    up[2]=fpair(v0.z,v1.z);   up[3]=fpair(v0.w,v1.w);

    const ulonglong2* M2 = (const ulonglong2*)&sM[mi*256];
    const ulonglong2* K2 = (const ulonglong2*)&sK[mi*128];
    const ulonglong2* N2 = (const ulonglong2*)&sN[mi*64];
    ull acc[SDIM];
    #pragma unroll
    for (int s=0;s<SDIM;s++){
      ulonglong2 k0p = K2[s*4+0];
      ull a = 0ull;
      ffma2(a, k0p.x, zp[0]); ffma2(a, k0p.y, zp[1]);
      ulonglong2 k1p = K2[s*4+1]; ffma2(a, k1p.x, zp[2]); ffma2(a, k1p.y, zp[3]);
      ulonglong2 k2p = K2[s*4+2]; ffma2(a, k2p.x, zp[4]); ffma2(a, k2p.y, zp[5]);
      ulonglong2 k3p = K2[s*4+3]; ffma2(a, k3p.x, zp[6]); ffma2(a, k3p.y, zp[7]);
      ulonglong2 n0p = N2[s*2+0]; ffma2(a, n0p.x, up[0]); ffma2(a, n0p.y, up[1]);
      ulonglong2 n1p = N2[s*2+1]; ffma2(a, n1p.x, up[2]); ffma2(a, n1p.y, up[3]);
      acc[s]=a;
    }
    #pragma unroll
    for (int s=0;s<SDIM;s++){
      ull a = acc[s];
      #pragma unroll
      for (int jj=0;jj<8;jj++){
        ulonglong2 mm = M2[s*8+jj];
        ffma2(a, mm.x, xp[2*jj]);
        ffma2(a, mm.y, xp[2*jj+1]);
      }
      acc[s]=a;
    }
    #pragma unroll
    for (int s=0;s<SDIM;s++) xp[s]=acc[s];

    {
      float a0[SDIM], a1[SDIM];
      #pragma unroll
      for (int s=0;s<SDIM;s++) unpack2(xp[s], a0[s], a1[s]);
      float* o0 = out + (((size_t)b0*T_SEQ) + (size_t)(k0+i))*SDIM;
      float* o1 = out + (((size_t)(b0+1)*T_SEQ) + (size_t)(k0+i))*SDIM;
      stg256(o0,     a0);
      stg256(o0 + 8, a0 + 8);
      stg256(o1,     a1);
      stg256(o1 + 8, a1 + 8);
    }
  }
}

extern "C" void kernel_launch(void* const* d_in, const int* in_sizes, int n_in,
                              void* d_out, int out_size)
{
  const float* obs = (const float*)d_in[0];
  const float* u   = (const float*)d_in[1];
  const float* A   = (const float*)d_in[2];
  const float* B   = (const float*)d_in[3];
  const float* C   = (const float*)d_in[4];
  const float* Q   = (const float*)d_in[5];
  const float* R   = (const float*)d_in[6];
  const float* x0  = (const float*)d_in[7];
  float* out = (float*)d_out;

  riccati_kernel<<<1, 256>>>(A, B, C, Q, R);

  dim3 gridR(BATCH/(TPB*NB), CH);
  resp_kernel<<<gridR, TPB>>>(obs, u);
  pass2_kernel<<<BATCH/TPB, TPB>>>(x0);
  pass3_kernel<<<gridR, TPB>>>(obs, u, out);
}

// round 15
// speedup vs baseline: 1.5342x; 1.3379x over previous
#include <cuda_runtime.h>
#include <cstdint>
#include <cstddef>

#define BATCH 4096
#define T_SEQ 512
#define SDIM  16
#define ODIM  8
#define IDIM  4
#define RS    8
#define CH    64
#define LCH   8
#define NB    2
#define TPB   128
#define NTYPE 2

typedef unsigned long long ull;

__device__ float g_M [RS*256];
__device__ float g_Kg[RS*128];
__device__ float g_Ng[RS*64];
__device__ float g_Phi[NTYPE*256];
__device__ float g_W  [NTYPE*16*96];            // [type][s][j*12 + q] (q: 0..7 z, 8..11 u)
__device__ float g_d [(size_t)CH*SDIM*BATCH];   // [c][s][b]
__device__ float g_xs[(size_t)CH*SDIM*BATCH];   // [c][s][b]

// ---------- f32x2 helpers ----------
__device__ __forceinline__ ull fpair(float a, float b){
  ull r; asm("mov.b64 %0, {%1,%2};" : "=l"(r) : "f"(a), "f"(b)); return r;
}
__device__ __forceinline__ ull fdup(float a){ return fpair(a,a); }
__device__ __forceinline__ void unpack2(ull p, float& a, float& b){
  asm("mov.b64 {%0,%1}, %2;" : "=f"(a), "=f"(b) : "l"(p));
}
__device__ __forceinline__ void ffma2(ull& d, ull a, ull b){
  asm("fma.rn.f32x2 %0, %1, %2, %0;" : "+l"(d) : "l"(a), "l"(b));
}

// ---------- 256-bit global memory ops (sm_100+) ----------
__device__ __forceinline__ void ldg256(float* r, const float* p){
  asm("ld.global.v8.f32 {%0,%1,%2,%3,%4,%5,%6,%7}, [%8];"
      : "=f"(r[0]),"=f"(r[1]),"=f"(r[2]),"=f"(r[3]),
        "=f"(r[4]),"=f"(r[5]),"=f"(r[6]),"=f"(r[7])
      : "l"(p));
}
__device__ __forceinline__ void stg256(float* p, const float* r){
  asm volatile("st.global.v8.f32 [%0], {%1,%2,%3,%4,%5,%6,%7,%8};"
      :: "l"(p),
         "f"(r[0]),"f"(r[1]),"f"(r[2]),"f"(r[3]),
         "f"(r[4]),"f"(r[5]),"f"(r[6]),"f"(r[7])
      : "memory");
}

// K1: Riccati (8 exact steps, Gauss-Jordan S-inverse) + W/Phi composition. 1 block, 256 thr.
__global__ void riccati_kernel(const float* __restrict__ A_, const float* __restrict__ B_,
                               const float* __restrict__ C_, const float* __restrict__ Q_,
                               const float* __restrict__ R_)
{
  __shared__ float sA[256], sQ[256], sC[128], sB[64], sR[64], sCA[128], sCB[32];
  __shared__ float P[256], Tm[256], Pp[256], CP[128], S8[64], Inv8[64], KK[128];
  __shared__ float BufA[256], BufB[256];
  __shared__ float sMh[RS*256], sKh[RS*128], sNh[RS*64];
  const int t = threadIdx.x;
  const int s = t>>4, j = t&15;

  sA[t]=A_[t]; sQ[t]=Q_[t];
  P[t] = (s==j)?1.f:0.f;
  if (t<128) sC[t]=C_[t];
  if (t<64){ sB[t]=B_[t]; sR[t]=R_[t]; }
  __syncthreads();
  if (t<128){ int o=t>>4, jj=t&15; float a=0.f;
    #pragma unroll
    for(int m=0;m<16;m++) a+=sC[o*16+m]*sA[m*16+jj];
    sCA[t]=a; }
  if (t<32){ int o=t>>2, ii=t&3; float a=0.f;
    #pragma unroll
    for(int m=0;m<16;m++) a+=sC[o*16+m]*sB[m*4+ii];
    sCB[t]=a; }
  __syncthreads();

  for (int k=0;k<RS;k++){
    { float a=0.f;                                    // Tm = A @ P
      #pragma unroll
      for(int m=0;m<16;m++) a+=sA[s*16+m]*P[m*16+j];
      Tm[t]=a; }
    __syncthreads();
    { float a=sQ[t];                                  // Pp = Tm A^T + Q
      #pragma unroll
      for(int m=0;m<16;m++) a+=Tm[s*16+m]*sA[j*16+m];
      Pp[t]=a; }
    __syncthreads();
    if (t<128){ int o=t>>4, jj=t&15; float a=0.f;     // CP = C @ Pp
      #pragma unroll
      for(int m=0;m<16;m++) a+=sC[o*16+m]*Pp[m*16+jj];
      CP[t]=a; }
    __syncthreads();
    if (t<64){ int o=t>>3, p=t&7; float a=sR[t];      // S = CP C^T + R
      #pragma unroll
      for(int m=0;m<16;m++) a+=CP[o*16+m]*sC[p*16+m];
      S8[t]=a;
      Inv8[t]=(o==p)?1.f:0.f; }
    __syncthreads();
    for (int p=0;p<8;p++){                            // Gauss-Jordan (SPD, no pivoting)
      if (t<64 && (t>>3)==p){
        float rp = 1.f/S8[p*8+p];
        S8[t]*=rp; Inv8[t]*=rp;
      }
      __syncthreads();
      float f=0.f, spc=0.f, sic=0.f, so=0.f, io=0.f;
      if (t<64){
        f=S8[(t>>3)*8+p]; spc=S8[p*8+(t&7)]; sic=Inv8[p*8+(t&7)]; so=S8[t]; io=Inv8[t]; }
      __syncthreads();
      if (t<64 && (t>>3)!=p){
        S8[t]=so-f*spc; Inv8[t]=io-f*sic;
      }
      __syncthreads();
    }
    if (t<128){ int ss=t>>3, o=t&7; float a=0.f;      // K = CP^T Sinv
      #pragma unroll
      for(int p=0;p<8;p++) a+=CP[p*16+ss]*Inv8[p*8+o];
      KK[t]=a; }
    __syncthreads();
    { float a=Pp[t], mg=sA[t];                        // P_post, M_k
      #pragma unroll
      for(int o=0;o<8;o++){ float kv=KK[s*8+o]; a-=kv*CP[o*16+j]; mg-=kv*sCA[o*16+j]; }
      P[t]=a;
      sMh[k*256+t]=mg; g_M[k*256+t]=mg; }
    if (t<128){ sKh[k*128+t]=KK[t]; g_Kg[k*128+t]=KK[t]; }
    if (t<64){ int ss=t>>2, ii=t&3; float a=sB[t];    // N_k
      #pragma unroll
      for(int o=0;o<8;o++) a-=KK[ss*8+o]*sCB[o*4+ii];
      sNh[k*64+t]=a; g_Ng[k*64+t]=a; }
    __syncthreads();
  }

  for (int tt=0; tt<NTYPE; tt++){                     // W + Phi per chunk type
    float* Sb = BufA; float* Sn = BufB;
    Sb[t] = (s==j)?1.f:0.f;
    __syncthreads();
    for (int jj=LCH-1; jj>=0; jj--){
      const int k = (tt==0)? jj : (RS-1);
      if (t<128){ int ss=t>>3, o=t&7; float a=0.f;    // Wz
        #pragma unroll
        for(int m=0;m<16;m++) a+=Sb[ss*16+m]*sKh[k*128+m*8+o];
        g_W[(tt*16+ss)*96 + jj*12 + o] = a; }
      else { int e=t-128; int ss=e>>2, ii=e&3;        // Wu
        if (e<64){ float a=0.f;
          #pragma unroll
          for(int m=0;m<16;m++) a+=Sb[ss*16+m]*sNh[k*64+m*4+ii];
          g_W[(tt*16+ss)*96 + jj*12 + 8 + ii] = a; } }
      { float a=0.f;                                  // S = S @ M_k
        #pragma unroll
        for(int m=0;m<16;m++) a+=Sb[s*16+m]*sMh[k*256+m*16+j];
        Sn[t]=a; }
      __syncthreads();
      float* tmp=Sb; Sb=Sn; Sn=tmp;
    }
    g_Phi[tt*256+t]=Sb[t];
    __syncthreads();
  }
}

// P1: chunk response from zero state; z via 256-bit loads, u paired over 2 steps.
__global__ void __launch_bounds__(TPB) resp_kernel(const float* __restrict__ obs,
                                                   const float* __restrict__ u)
{
  __shared__ ull sW[16*96];
  const int c  = blockIdx.y;
  const int tt = (c==0)?0:1;
  for (int idx=threadIdx.x; idx<16*96; idx+=TPB)
    sW[idx] = fdup(g_W[tt*16*96 + idx]);
  const int b0 = (blockIdx.x*TPB + threadIdx.x)*NB;
  const int k0 = c*LCH;
  ull acc[SDIM];
  #pragma unroll
  for (int s=0;s<SDIM;s++) acc[s]=0ull;
  __syncthreads();

  const float* ob0 = obs + ((size_t)b0*T_SEQ + k0)*ODIM;
  const float* ob1 = ob0 + (size_t)T_SEQ*ODIM;
  const float* uu0 = u   + ((size_t)b0*T_SEQ + k0)*IDIM;
  const float* uu1 = uu0 + (size_t)T_SEQ*IDIM;

  for (int jj=0;jj<LCH;jj+=2){
    float ua0[8], ua1[8];                      // u for steps jj, jj+1 (32B contiguous)
    ldg256(ua0, uu0 + jj*IDIM);
    ldg256(ua1, uu1 + jj*IDIM);
    #pragma unroll
    for (int h=0;h<2;h++){
      const int j2 = jj+h;
      float z0[8], z1[8];
      ldg256(z0, ob0 + j2*ODIM);
      ldg256(z1, ob1 + j2*ODIM);
      ull ip[12];
      #pragma unroll
      for (int q=0;q<8;q++) ip[q]=fpair(z0[q],z1[q]);
      #pragma unroll
      for (int q=0;q<4;q++) ip[8+q]=fpair(ua0[h*4+q],ua1[h*4+q]);
      #pragma unroll
      for (int s=0;s<SDIM;s++){
        const ulonglong2* Wr = (const ulonglong2*)&sW[s*96 + j2*12];
        ull a = acc[s];
        #pragma unroll
        for (int q=0;q<6;q++){
          ulonglong2 w = Wr[q];
          ffma2(a, w.x, ip[2*q]);
          ffma2(a, w.y, ip[2*q+1]);
        }
        acc[s]=a;
      }
    }
  }
  #pragma unroll
  for (int s=0;s<SDIM;s++)
    *(ull*)&g_d[((size_t)(c*SDIM+s))*BATCH + b0] = acc[s];
}

// P2 v2: one thread per (batch, state). 8 batches x 16 states per block, smem x-exchange.
__global__ void __launch_bounds__(TPB) pass2_kernel(const float* __restrict__ x0)
{
  __shared__ float sPhi[NTYPE*256];
  __shared__ float sX[TPB];                   // [s][b_local] : s*8 + bl
  for (int e=threadIdx.x; e<NTYPE*256; e+=TPB) sPhi[e]=g_Phi[e];
  const int t  = threadIdx.x;
  const int s  = t>>3;                        // 0..15
  const int bl = t&7;                         // 0..7
  const int b  = blockIdx.x*8 + bl;
  float x = x0[s];
  __syncthreads();
  g_xs[(size_t)s*BATCH + b] = x;
  for (int c=1;c<CH;c++){
    sX[s*8+bl] = x;
    const float* Phi = &sPhi[((c-1==0)?0:1)*256 + s*16];
    float dd = g_d[((size_t)((c-1)*16+s))*BATCH + b];
    __syncthreads();
    float a = dd;
    #pragma unroll
    for (int jj=0;jj<16;jj++) a += Phi[jj]*sX[jj*8+bl];
    __syncthreads();
    x = a;
    g_xs[((size_t)(c*16+s))*BATCH + b] = x;
  }
}

// P3 (R14 body, verbatim): 256-bit z loads + 256-bit output stores.
__global__ void __launch_bounds__(TPB, 4) pass3_kernel(const float* __restrict__ obs,
                                                       const float* __restrict__ u,
                                                       float* __restrict__ out)
{
  __shared__ ull sM[LCH*256], sK[LCH*128], sN[LCH*64];  // 28KB
  const int tid = threadIdx.x;
  const int c  = blockIdx.y;
  const bool trans = (c==0);
  const int nset = trans ? LCH : 1;
  for (int idx=tid; idx<nset*256; idx+=TPB){
    int i=idx>>8, e=idx&255; int kk = trans ? i : (RS-1);
    sM[idx]=fdup(g_M[kk*256+e]);
  }
  for (int idx=tid; idx<nset*128; idx+=TPB){
    int i=idx>>7, e=idx&127; int kk = trans ? i : (RS-1);
    sK[idx]=fdup(g_Kg[kk*128+e]);
  }
  for (int idx=tid; idx<nset*64; idx+=TPB){
    int i=idx>>6, e=idx&63; int kk = trans ? i : (RS-1);
    sN[idx]=fdup(g_Ng[kk*64+e]);
  }
  const int b0 = blockIdx.x*(TPB*NB) + tid*NB;
  const int k0 = c*LCH;
  ull xp[SDIM];
  #pragma unroll
  for (int s=0;s<SDIM;s++)
    xp[s] = *(const ull*)&g_xs[((size_t)(c*SDIM+s))*BATCH + b0];
  __syncthreads();

  const float* ob0 = obs + ((size_t)b0*T_SEQ + k0)*ODIM;
  const float* ob1 = ob0 + (size_t)T_SEQ*ODIM;
  const float* uu0 = u   + ((size_t)b0*T_SEQ + k0)*IDIM;
  const float* uu1 = uu0 + (size_t)T_SEQ*IDIM;

  for (int i=0;i<LCH;i++){
    const int mi = trans ? i : 0;
    float z0[8], z1[8];
    ldg256(z0, ob0 + i*ODIM);
    ldg256(z1, ob1 + i*ODIM);
    float4 v0  = *(const float4*)(uu0 + i*IDIM);
    float4 v1  = *(const float4*)(uu1 + i*IDIM);
    ull zp[8], up[4];
    #pragma unroll
    for (int q=0;q<8;q++) zp[q]=fpair(z0[q],z1[q]);
    up[0]=fpair(v0.x,v1.x);   up[1]=fpair(v0.y,v1.y);
    up[2]=fpair(v0.z,v1.z);   up[3]=fpair(v0.w,v1.w);

    const ulonglong2* M2 = (const ulonglong2*)&sM[mi*256];
    const ulonglong2* K2 = (const ulonglong2*)&sK[mi*128];
    const ulonglong2* N2 = (const ulonglong2*)&sN[mi*64];
    ull acc[SDIM];
    #pragma unroll
    for (int s=0;s<SDIM;s++){
      ulonglong2 k0p = K2[s*4+0];
      ull a = 0ull;
      ffma2(a, k0p.x, zp[0]); ffma2(a, k0p.y, zp[1]);
      ulonglong2 k1p = K2[s*4+1]; ffma2(a, k1p.x, zp[2]); ffma2(a, k1p.y, zp[3]);
      ulonglong2 k2p = K2[s*4+2]; ffma2(a, k2p.x, zp[4]); ffma2(a, k2p.y, zp[5]);
      ulonglong2 k3p = K2[s*4+3]; ffma2(a, k3p.x, zp[6]); ffma2(a, k3p.y, zp[7]);
      ulonglong2 n0p = N2[s*2+0]; ffma2(a, n0p.x, up[0]); ffma2(a, n0p.y, up[1]);
      ulonglong2 n1p = N2[s*2+1]; ffma2(a, n1p.x, up[2]); ffma2(a, n1p.y, up[3]);
      acc[s]=a;
    }
    #pragma unroll
    for (int s=0;s<SDIM;s++){
      ull a = acc[s];
      #pragma unroll
      for (int jj=0;jj<8;jj++){
        ulonglong2 mm = M2[s*8+jj];
        ffma2(a, mm.x, xp[2*jj]);
        ffma2(a, mm.y, xp[2*jj+1]);
      }
      acc[s]=a;
    }
    #pragma unroll
    for (int s=0;s<SDIM;s++) xp[s]=acc[s];

    {
      float a0[SDIM], a1[SDIM];
      #pragma unroll
      for (int s=0;s<SDIM;s++) unpack2(xp[s], a0[s], a1[s]);
      float* o0 = out + (((size_t)b0*T_SEQ) + (size_t)(k0+i))*SDIM;
      float* o1 = out + (((size_t)(b0+1)*T_SEQ) + (size_t)(k0+i))*SDIM;
      stg256(o0,     a0);
      stg256(o0 + 8, a0 + 8);
      stg256(o1,     a1);
      stg256(o1 + 8, a1 + 8);
    }
  }
}

extern "C" void kernel_launch(void* const* d_in, const int* in_sizes, int n_in,
                              void* d_out, int out_size)
{
  const float* obs = (const float*)d_in[0];
  const float* u   = (const float*)d_in[1];
  const float* A   = (const float*)d_in[2];
  const float* B   = (const float*)d_in[3];
  const float* C   = (const float*)d_in[4];
  const float* Q   = (const float*)d_in[5];
  const float* R   = (const float*)d_in[6];
  const float* x0  = (const float*)d_in[7];
  float* out = (float*)d_out;

  riccati_kernel<<<1, 256>>>(A, B, C, Q, R);

  dim3 gridR(BATCH/(TPB*NB), CH);
  resp_kernel<<<gridR, TPB>>>(obs, u);
  pass2_kernel<<<BATCH*SDIM/TPB, TPB>>>(x0);
  pass3_kernel<<<gridR, TPB>>>(obs, u, out);
}